// round 2
// baseline (speedup 1.0000x reference)
#include <cuda_runtime.h>

// Coefficient matrix for the exact factorization
//   out(x0,x1) = [1, cos x0, sin x0] * B * [1, cos x1, sin x1]^T
// computed on-device by prep_kernel (weights are shared across the batch).
// Rows padded to 4 floats for one aligned float4 load each.
__device__ __align__(16) float g_B[12];

struct C2 { float re, im; };

// Apply RX-pair [c, -i*sn; -i*sn, c] to amplitudes (a0, a1), given
// c = cos(theta/2), sn = sin(theta/2).
__device__ __forceinline__ void rx_pair(float c, float sn, C2 &a0, C2 &a1) {
    C2 n0, n1;
    n0.re = c * a0.re + sn * a1.im;
    n0.im = c * a0.im - sn * a1.re;
    n1.re = c * a1.re + sn * a0.im;
    n1.im = c * a1.im - sn * a0.re;
    a0 = n0; a1 = n1;
}

// Simulate the reference circuit for one (x0, x1) where the half-angle
// sincos of the encoding angles AND of the 4 weights are precomputed.
__device__ float sim_circuit_pre(float c0, float s0,   // cos/sin(x0/2)
                                 float c1, float s1,   // cos/sin(x1/2)
                                 const float* cw, const float* sw) {
    C2 s00 = {1.f, 0.f}, s01 = {0.f, 0.f}, s10 = {0.f, 0.f}, s11 = {0.f, 0.f};

    // Data encoding: RX(x0) on qubit 0 (rows), RX(x1) on qubit 1 (cols)
    rx_pair(c0, s0, s00, s10); rx_pair(c0, s0, s01, s11);
    rx_pair(c1, s1, s00, s01); rx_pair(c1, s1, s10, s11);

    // Two variational layers: RX(w[l,0]) q0, RX(w[l,1]) q1, CNOT(0->1)
    #pragma unroll
    for (int l = 0; l < 2; l++) {
        rx_pair(cw[2*l+0], sw[2*l+0], s00, s10);
        rx_pair(cw[2*l+0], sw[2*l+0], s01, s11);
        rx_pair(cw[2*l+1], sw[2*l+1], s00, s01);
        rx_pair(cw[2*l+1], sw[2*l+1], s10, s11);
        C2 t = s10; s10 = s11; s11 = t;  // CNOT: swap |10> <-> |11>
    }

    float p0 = s00.re*s00.re + s00.im*s00.im + s01.re*s01.re + s01.im*s01.im;
    float p1 = s10.re*s10.re + s10.im*s10.im + s11.re*s11.re + s11.im*s11.im;
    return 0.5f * ((p0 - p1) + 1.0f);
}

// Evaluate the circuit at the 9 grid points {0, pi/2, pi}^2 and solve the
// trivially-conditioned 3x3 basis system for B. Half-angle sincos of the
// grid thetas are compile-time constants: theta/2 in {0, pi/4, pi/2} ->
// (cos,sin) = (1,0), (r2,r2), (0,1) with r2 = sqrt(2)/2.
// Basis f(theta) = (1, cos t, sin t): f(0)=(1,1,0), f(pi/2)=(1,0,1),
// f(pi)=(1,-1,0). r0=a+b, r1=a+c, r2=a-b => a=(r0+r2)/2, b=(r0-r2)/2, c=r1-a.
__global__ void prep_kernel(const float* __restrict__ w) {
    if (threadIdx.x != 0 || blockIdx.x != 0) return;

    // Only 4 runtime trig calls (the shared weights).
    float cw[4], sw[4];
    #pragma unroll
    for (int i = 0; i < 4; i++) {
        cw[i] = cosf(0.5f * w[i]);
        sw[i] = sinf(0.5f * w[i]);
    }

    const float r2 = 0.70710678118654752440f;
    const float gc[3] = {1.f, r2, 0.f};   // cos(theta/2) for theta = 0, pi/2, pi
    const float gs[3] = {0.f, r2, 1.f};   // sin(theta/2)

    float R[3][3];
    #pragma unroll
    for (int i = 0; i < 3; i++)
        #pragma unroll
        for (int j = 0; j < 3; j++)
            R[i][j] = sim_circuit_pre(gc[i], gs[i], gc[j], gs[j], cw, sw);

    float H[3][3];  // invert along the x0 axis
    #pragma unroll
    for (int j = 0; j < 3; j++) {
        H[0][j] = 0.5f * (R[0][j] + R[2][j]);
        H[1][j] = 0.5f * (R[0][j] - R[2][j]);
        H[2][j] = R[1][j] - H[0][j];
    }
    #pragma unroll
    for (int p = 0; p < 3; p++) {  // invert along the x1 axis
        float b0 = 0.5f * (H[p][0] + H[p][2]);
        g_B[4*p + 0] = b0;
        g_B[4*p + 1] = 0.5f * (H[p][0] - H[p][2]);
        g_B[4*p + 2] = H[p][1] - b0;
        g_B[4*p + 3] = 0.f;
    }
}

__device__ __forceinline__ float eval_one(float x0, float x1,
                                          float4 B0, float4 B1, float4 B2) {
    float s0, c0, s1, c1;
    __sincosf(x0, &s0, &c0);
    __sincosf(x1, &s1, &c1);
    float t0 = fmaf(B0.z, s1, fmaf(B0.y, c1, B0.x));
    float t1 = fmaf(B1.z, s1, fmaf(B1.y, c1, B1.x));
    float t2 = fmaf(B2.z, s1, fmaf(B2.y, c1, B2.x));
    return fmaf(t2, s0, fmaf(t1, c0, t0));
}

// 4 samples per thread: 2x LDG.128 in, 1x STG.128 out. Memory-bound;
// MUFU (16 instrs/thread-warp) hides under the ~7.6k-cycle DRAM time.
__global__ void __launch_bounds__(256)
quantum_main_kernel(const float4* __restrict__ x, float4* __restrict__ out,
                    int nthreads) {
    int i = blockIdx.x * blockDim.x + threadIdx.x;
    if (i >= nthreads) return;

    const float4* Bv = reinterpret_cast<const float4*>(g_B);
    float4 B0 = Bv[0];
    float4 B1 = Bv[1];
    float4 B2 = Bv[2];

    float4 xa = x[2*i + 0];  // samples 4i, 4i+1 : (x0,x1,x0,x1)
    float4 xb = x[2*i + 1];  // samples 4i+2, 4i+3

    float4 r;
    r.x = eval_one(xa.x, xa.y, B0, B1, B2);
    r.y = eval_one(xa.z, xa.w, B0, B1, B2);
    r.z = eval_one(xb.x, xb.y, B0, B1, B2);
    r.w = eval_one(xb.z, xb.w, B0, B1, B2);

    out[i] = r;
}

extern "C" void kernel_launch(void* const* d_in, const int* in_sizes, int n_in,
                              void* d_out, int out_size) {
    const float* x = (const float*)d_in[0];   // [B, 2] float32
    const float* w = (const float*)d_in[1];   // [N_LAYERS=2, 2] float32
    float* out = (float*)d_out;               // [B, 1] float32

    prep_kernel<<<1, 32>>>(w);

    int nsamples = in_sizes[0] / 2;           // B = 4194304
    int nthreads = nsamples / 4;              // 4 samples per thread
    int blocks = (nthreads + 255) / 256;
    quantum_main_kernel<<<blocks, 256>>>(
        (const float4*)x, (float4*)out, nthreads);
}

// round 7
// speedup vs baseline: 1.1224x; 1.1224x over previous
#include <cuda_runtime.h>

struct C2 { float re, im; };

// Apply RX-pair [c, -i*sn; -i*sn, c] to amplitudes (a0, a1), given
// c = cos(theta/2), sn = sin(theta/2).
__device__ __forceinline__ void rx_pair(float c, float sn, C2 &a0, C2 &a1) {
    C2 n0, n1;
    n0.re = c * a0.re + sn * a1.im;
    n0.im = c * a0.im - sn * a1.re;
    n1.re = c * a1.re + sn * a0.im;
    n1.im = c * a1.im - sn * a0.re;
    a0 = n0; a1 = n1;
}

// Simulate the reference circuit for one (x0, x1), with half-angle sincos of
// the encoding angles and of the 4 shared weights precomputed.
__device__ __forceinline__ float sim_circuit_pre(
        float c0, float s0,          // cos/sin(x0/2)
        float c1, float s1,          // cos/sin(x1/2)
        const float* cw, const float* sw) {
    C2 s00 = {1.f, 0.f}, s01 = {0.f, 0.f}, s10 = {0.f, 0.f}, s11 = {0.f, 0.f};

    // Data encoding: RX(x0) on qubit 0 (rows), RX(x1) on qubit 1 (cols)
    rx_pair(c0, s0, s00, s10); rx_pair(c0, s0, s01, s11);
    rx_pair(c1, s1, s00, s01); rx_pair(c1, s1, s10, s11);

    // Two variational layers: RX(w[l,0]) q0, RX(w[l,1]) q1, CNOT(0->1)
    #pragma unroll
    for (int l = 0; l < 2; l++) {
        rx_pair(cw[2*l+0], sw[2*l+0], s00, s10);
        rx_pair(cw[2*l+0], sw[2*l+0], s01, s11);
        rx_pair(cw[2*l+1], sw[2*l+1], s00, s01);
        rx_pair(cw[2*l+1], sw[2*l+1], s10, s11);
        C2 t = s10; s10 = s11; s11 = t;   // CNOT: swap |10> <-> |11>
    }

    float p0 = s00.re*s00.re + s00.im*s00.im + s01.re*s01.re + s01.im*s01.im;
    float p1 = s10.re*s10.re + s10.im*s10.im + s11.re*s11.re + s11.im*s11.im;
    return 0.5f * ((p0 - p1) + 1.0f);
}

__device__ __forceinline__ float2 eval_pair(float4 q,
                                            float4 B0, float4 B1, float4 B2) {
    float2 r;
    #pragma unroll
    for (int k = 0; k < 2; k++) {
        float x0 = k ? q.z : q.x;
        float x1 = k ? q.w : q.y;
        float s0, c0, s1, c1;
        __sincosf(x0, &s0, &c0);
        __sincosf(x1, &s1, &c1);
        float t0 = fmaf(B0.z, s1, fmaf(B0.y, c1, B0.x));
        float t1 = fmaf(B1.z, s1, fmaf(B1.y, c1, B1.x));
        float t2 = fmaf(B2.z, s1, fmaf(B2.y, c1, B2.x));
        float v  = fmaf(t2, s0, fmaf(t1, c0, t0));
        if (k) r.y = v; else r.x = v;
    }
    return r;
}

// Per-block prep: warp 0 computes the exact 3x3 bilinear factorization
//   out(x0,x1) = [1,cos x0,sin x0] * B * [1,cos x1,sin x1]^T
// by evaluating the reference circuit at the 9 grid points {0, pi/2, pi}^2
// (half-angle sincos are compile-time constants) and inverting the
// trivially-conditioned basis. Lanes 0..8 each simulate one grid point.
__device__ __forceinline__ void compute_B(const float* __restrict__ w,
                                          int lane, float* sR, float* sB) {
    float cw[4], sw[4];
    #pragma unroll
    for (int k = 0; k < 4; k++)
        __sincosf(0.5f * __ldg(w + k), &sw[k], &cw[k]);

    const float r2c = 0.70710678118654752440f;
    int li = lane / 3;            // grid index along x0 (lanes 0..8 valid)
    int lj = lane - 3 * li;       // grid index along x1
    // theta/2 in {0, pi/4, pi/2} -> (cos,sin) = (1,0), (r2,r2), (0,1)
    float ci = (li == 0) ? 1.f : ((li == 1) ? r2c : 0.f);
    float si = (li == 0) ? 0.f : ((li == 1) ? r2c : 1.f);
    float cj = (lj == 0) ? 1.f : ((lj == 1) ? r2c : 0.f);
    float sj = (lj == 0) ? 0.f : ((lj == 1) ? r2c : 1.f);

    float Rv = sim_circuit_pre(ci, si, cj, sj, cw, sw);
    if (lane < 9) sR[lane] = Rv;
    __syncwarp();

    if (lane == 0) {
        // Basis f(t) = (1, cos t, sin t): f(0)=(1,1,0), f(pi/2)=(1,0,1),
        // f(pi)=(1,-1,0). r0=a+b, r1=a+c, r2=a-b.
        float H[3][3];
        #pragma unroll
        for (int j = 0; j < 3; j++) {
            H[0][j] = 0.5f * (sR[0 + j] + sR[6 + j]);
            H[1][j] = 0.5f * (sR[0 + j] - sR[6 + j]);
            H[2][j] = sR[3 + j] - H[0][j];
        }
        #pragma unroll
        for (int p = 0; p < 3; p++) {
            float b0 = 0.5f * (H[p][0] + H[p][2]);
            sB[4*p + 0] = b0;
            sB[4*p + 1] = 0.5f * (H[p][0] - H[p][2]);
            sB[4*p + 2] = H[p][1] - b0;
            sB[4*p + 3] = 0.f;
        }
    }
}

// Exact-size kernel (grid * 256 == nthreads): no bounds predicate anywhere,
// so the 4 LDG.128 issue unconditionally back-to-back (MLP_p1 = 4).
// Warp-interleaved layout: each LDG.128 is lane-contiguous 512B across the
// warp; warp covers 128 consecutive float4 (2KB).
__global__ void __launch_bounds__(256)
quantum_fused_exact(const float4* __restrict__ x,
                    float2* __restrict__ out,
                    const float* __restrict__ w) {
    __shared__ __align__(16) float sB[12];
    __shared__ float sR[9];

    int g = blockIdx.x * blockDim.x + threadIdx.x;
    int lane = threadIdx.x & 31;
    int base = (g >> 5) * 128 + lane;

    // Unconditional global loads issue FIRST; prep math overlaps DRAM latency.
    float4 xa = x[base];
    float4 xb = x[base + 32];
    float4 xc = x[base + 64];
    float4 xd = x[base + 96];

    if (threadIdx.x < 32)
        compute_B(w, lane, sR, sB);
    __syncthreads();

    const float4* Bv = reinterpret_cast<const float4*>(sB);
    float4 B0 = Bv[0];
    float4 B1 = Bv[1];
    float4 B2 = Bv[2];

    // Each float4 of x holds 2 samples: (x0,x1,x0',x1') -> 2 outputs.
    out[base +  0] = eval_pair(xa, B0, B1, B2);
    out[base + 32] = eval_pair(xb, B0, B1, B2);
    out[base + 64] = eval_pair(xc, B0, B1, B2);
    out[base + 96] = eval_pair(xd, B0, B1, B2);
}

// Guarded fallback for sizes that don't divide evenly (not hit for B=4M).
__global__ void __launch_bounds__(256)
quantum_fused_guarded(const float4* __restrict__ x,
                      float2* __restrict__ out,
                      const float* __restrict__ w,
                      int nthreads) {
    __shared__ __align__(16) float sB[12];
    __shared__ float sR[9];

    int g = blockIdx.x * blockDim.x + threadIdx.x;
    int lane = threadIdx.x & 31;
    bool active = (g < nthreads);
    int base = (g >> 5) * 128 + lane;

    float4 xa = {}, xb = {}, xc = {}, xd = {};
    if (active) {
        xa = x[base];
        xb = x[base + 32];
        xc = x[base + 64];
        xd = x[base + 96];
    }

    if (threadIdx.x < 32)
        compute_B(w, lane, sR, sB);
    __syncthreads();

    if (!active) return;

    const float4* Bv = reinterpret_cast<const float4*>(sB);
    float4 B0 = Bv[0];
    float4 B1 = Bv[1];
    float4 B2 = Bv[2];

    out[base +  0] = eval_pair(xa, B0, B1, B2);
    out[base + 32] = eval_pair(xb, B0, B1, B2);
    out[base + 64] = eval_pair(xc, B0, B1, B2);
    out[base + 96] = eval_pair(xd, B0, B1, B2);
}

extern "C" void kernel_launch(void* const* d_in, const int* in_sizes, int n_in,
                              void* d_out, int out_size) {
    const float* x = (const float*)d_in[0];   // [B, 2] float32
    const float* w = (const float*)d_in[1];   // [N_LAYERS=2, 2] float32

    int nf4 = in_sizes[0] / 4;                // float4 count = B/2
    int nthreads = nf4 / 4;                   // 4 float4 (8 samples) / thread

    if ((nf4 % 4 == 0) && (nthreads % 256 == 0)) {
        // B = 4194304 -> nthreads = 524288 = 2048 blocks * 256, no tail.
        quantum_fused_exact<<<nthreads / 256, 256>>>(
            (const float4*)x, (float2*)d_out, w);
    } else {
        int blocks = (nthreads + 255) / 256;
        quantum_fused_guarded<<<blocks, 256>>>(
            (const float4*)x, (float2*)d_out, w, nthreads);
    }
}